// round 13
// baseline (speedup 1.0000x reference)
#include <cuda_runtime.h>

// TopicNounAttention — R11: warp-per-sample (1 warp = 1 CTA, R7 retirement fix)
// + explicit 4-token load/compute phase batching. R10 analysis: unroll-2 kept
// only ~1.9 lines in flight per warp (e-register WAR behind the 130cyc reduce
// + exp), so each 2-token group ate nearly full DRAM latency serially. 4-token
// batch at ~96 regs costs nothing here: 20 theoretical warps == 21 achieved
// today (R4's version of this lost because 128-thr CTAs collapsed to 12.7
// warps via slowest-warp retirement; that's fixed by 32-thr CTAs).
// Un-normalized softmax: scores O(1) by construction (k_w ~1/sqrt(312),
// q_w ~1/sqrt(128)) -> fp32 exp safe, bias terms cancel, month block = mie.

#define VOCAB   50000
#define D_WORD  300
#define D_TOPIC 128
#define DH      312
#define LMAX    32
#define TB      4      // token batch

__device__ __align__(16) float g_ws[320];  // scaled projection vector, zero-padded

__global__ void __launch_bounds__(1024) prep_kernel(
    const float* __restrict__ topic_emb,
    const float* __restrict__ k_w,
    const float* __restrict__ q_w,
    const float* __restrict__ q_b)
{
    __shared__ float q[D_TOPIC];
    const int tid  = threadIdx.x;
    const int warp = tid >> 5;
    const int lane = tid & 31;

    // phase 1: q = q_w @ topic_emb + q_b ; warp-per-4-outputs, lane-parallel K
    #pragma unroll
    for (int j = 0; j < 4; ++j) {
        const int t = warp * 4 + j;             // 0..127
        float s = 0.f;
        #pragma unroll
        for (int k = 0; k < 4; ++k) {
            const int i = lane + 32 * k;
            s += q_w[t * D_TOPIC + i] * topic_emb[i];
        }
        #pragma unroll
        for (int o = 16; o > 0; o >>= 1) s += __shfl_xor_sync(0xffffffffu, s, o);
        if (lane == 0) q[t] = s + q_b[t];
    }
    __syncthreads();

    // phase 2: g_ws[t] = scale * sum_i k_w[i][t] * q[i] ; thread-per-output,
    // 8 accumulators + full unroll -> deep MLP, coalesced over t
    const float scale = 0.0883883476483184406f;  // 1/sqrt(128)
    if (tid < 320) {
        float acc = 0.f;
        if (tid < DH) {
            float p[8] = {0.f, 0.f, 0.f, 0.f, 0.f, 0.f, 0.f, 0.f};
            #pragma unroll
            for (int i = 0; i < D_TOPIC; i += 8) {
                #pragma unroll
                for (int k = 0; k < 8; ++k)
                    p[k] += k_w[(i + k) * DH + tid] * q[i + k];
            }
            acc = (((p[0] + p[1]) + (p[2] + p[3])) + ((p[4] + p[5]) + (p[6] + p[7]))) * scale;
        }
        g_ws[tid] = acc;  // pads [312,320) with zero
    }
}

__device__ __forceinline__ float dot4(float4 a, float4 b) {
    return a.x * b.x + a.y * b.y + a.z * b.z + a.w * b.w;
}

__global__ void __launch_bounds__(32) attn_kernel(
    const int*   __restrict__ noun_ids,   // [B, 32]
    const int*   __restrict__ lengths,    // [B]
    const int*   __restrict__ months,     // [B]
    const void*  __restrict__ mie_ptr,    // scalar month_info_encode
    const float* __restrict__ we,         // [VOCAB, 300]
    float*       __restrict__ out)        // [B, 312]
{
    const int lane = threadIdx.x;
    const int b = blockIdx.x;

    float4* ob = reinterpret_cast<float4*>(out + (long long)b * DH);  // 1248B rows
    const int len0 = lengths[b];

    if (len0 <= 0) {
        const float4 z = make_float4(0.f, 0.f, 0.f, 0.f);
        ob[lane] = z; ob[lane + 32] = z;
        if (lane < 14) ob[lane + 64] = z;
        return;
    }
    const int len   = (len0 < LMAX) ? len0 : LMAX;
    const int month = months[b];
    const unsigned mu = *(const unsigned*)mie_ptr;
    const float mie = (mu < 0x10000u) ? (float)(int)mu : __uint_as_float(mu);

    // projection vector slice in registers (w2 zero-padded for lanes >= 11)
    const float4* wsv = reinterpret_cast<const float4*>(g_ws);
    const float4 w0 = wsv[lane];
    const float4 w1 = wsv[lane + 32];
    float4 w2 = make_float4(0.f, 0.f, 0.f, 0.f);
    const bool tail = (lane < 11);
    if (tail) w2 = wsv[lane + 64];

    const int ids = noun_ids[b * LMAX + lane];

    float4 a0 = make_float4(0.f, 0.f, 0.f, 0.f), a1 = a0, a2 = a0;
    float denom = 0.f;

    for (int l0 = 0; l0 < len; l0 += TB) {
        // phase A: 4 clamped row pointers (dead tokens reload row len-1 -> L1 hit,
        // no zero-fill, no divergence, no OOB)
        const float4* r[TB];
        #pragma unroll
        for (int k = 0; k < TB; ++k) {
            int lc = l0 + k;  lc = (lc < len) ? lc : (len - 1);
            r[k] = reinterpret_cast<const float4*>(
                we + (long long)__shfl_sync(0xffffffffu, ids, lc) * D_WORD);
        }

        // phase B: front-batch all 12 (11 for non-tail lanes) vector loads
        float4 e0[TB], e1[TB], e2[TB];
        #pragma unroll
        for (int k = 0; k < TB; ++k) {
            e0[k] = r[k][lane];
            e1[k] = r[k][lane + 32];
            if (tail) e2[k] = r[k][lane + 64];
        }

        // phase C: 4 independent dot + interleaved shfl reduces
        float s[TB];
        #pragma unroll
        for (int k = 0; k < TB; ++k) {
            s[k] = dot4(e0[k], w0) + dot4(e1[k], w1);
            if (tail) s[k] += dot4(e2[k], w2);
        }
        #pragma unroll
        for (int o = 16; o > 0; o >>= 1) {
            #pragma unroll
            for (int k = 0; k < TB; ++k)
                s[k] += __shfl_xor_sync(0xffffffffu, s[k], o);
        }

        // phase D: gate dead tokens, accumulate (a2 only meaningful on tail lanes)
        #pragma unroll
        for (int k = 0; k < TB; ++k) {
            const float p = (l0 + k < len) ? __expf(s[k]) : 0.f;
            denom += p;
            a0.x += p * e0[k].x;  a0.y += p * e0[k].y;
            a0.z += p * e0[k].z;  a0.w += p * e0[k].w;
            a1.x += p * e1[k].x;  a1.y += p * e1[k].y;
            a1.z += p * e1[k].z;  a1.w += p * e1[k].w;
            if (tail) {
                a2.x += p * e2[k].x;  a2.y += p * e2[k].y;
                a2.z += p * e2[k].z;  a2.w += p * e2[k].w;
            }
        }
    }

    const float inv = 1.f / denom;
    float4 o;
    o.x = a0.x * inv; o.y = a0.y * inv; o.z = a0.z * inv; o.w = a0.w * inv;
    ob[lane] = o;
    o.x = a1.x * inv; o.y = a1.y * inv; o.z = a1.z * inv; o.w = a1.w * inv;
    ob[lane + 32] = o;
    if (tail) {
        o.x = a2.x * inv; o.y = a2.y * inv; o.z = a2.z * inv; o.w = a2.w * inv;
        ob[lane + 64] = o;
    } else if (lane < 14) {
        const int j0 = 4 * lane + 256 - 300;   // month one-hot block d in [300,312)
        o.x = (j0 + 0 == month) ? mie : 0.f;
        o.y = (j0 + 1 == month) ? mie : 0.f;
        o.z = (j0 + 2 == month) ? mie : 0.f;
        o.w = (j0 + 3 == month) ? mie : 0.f;
        ob[lane + 64] = o;
    }
}

extern "C" void kernel_launch(void* const* d_in, const int* in_sizes, int n_in,
                              void* d_out, int out_size)
{
    const float* topic_emb = (const float*)d_in[0];
    const int*   noun_ids  = (const int*)  d_in[1];
    const int*   lengths   = (const int*)  d_in[2];
    const int*   months    = (const int*)  d_in[3];
    const void*  mie       = (const void*) d_in[4];
    const float* we        = (const float*)d_in[5];
    const float* k_w       = (const float*)d_in[6];
    const float* q_w       = (const float*)d_in[8];
    const float* q_b       = (const float*)d_in[9];
    float* out = (float*)d_out;

    const int B = in_sizes[2];

    prep_kernel<<<1, 1024>>>(topic_emb, k_w, q_w, q_b);
    attn_kernel<<<B, 32>>>(noun_ids, lengths, months, mie, we, out);
}